// round 12
// baseline (speedup 1.0000x reference)
#include <cuda_runtime.h>
#include <math.h>

// Problem constants (B,C,H,W,K) = (32,8,64,64,16)
#define BATCH 32
#define CHW    (8 * 64 * 64)           // 32768 elements per batch
#define N_ELEM (BATCH * CHW)           // 1,048,576
#define KMIX   16
#define TPB    128
#define NBLK   (N_ELEM / TPB)          // 8192 blocks

// Self-resetting cross-launch scratch (zero-initialized at module load; the
// kernel restores both to zero by the end of every launch -> every graph
// replay sees identical initial state).
__device__ float        g_acc[BATCH];
__device__ unsigned int g_done;

__global__ void __launch_bounds__(TPB)
coupling_kernel(const float*  __restrict__ x_change,
                const float*  __restrict__ x_id,
                const float*  __restrict__ sldj_in,
                const float*  __restrict__ a,
                const float*  __restrict__ b,
                const float4* __restrict__ pi4,
                const float4* __restrict__ mu4,
                const float4* __restrict__ s4,
                float* __restrict__ out,       // [N_ELEM]
                float* __restrict__ out_id,    // [N_ELEM]
                float* __restrict__ sldj_out)  // [BATCH]
{
    const int tid  = threadIdx.x;
    const int lane = tid & 31;
    const int i    = blockIdx.x * TPB + tid;

    // ---- streaming loads (single-use, evict-first) ----
    const float x = __ldcs(&x_change[i]);

    const int base4 = i * (KMIX / 4);   // float4 index, fully coalesced

    // Linear-domain mixture accumulation:
    //   e_k = exp(pi_k), es_k = exp(-s_k), z_k = (x-mu_k)*es_k
    //   t_k = exp(-z_k), sigma_k = 1/(1+t_k)
    //   S1 = sum e*sigma        (~ cdf * sum e)
    //   S0 = sum e*t*sigma      (~ (1-cdf)*sum e;  S1+S0 == sum e exactly)
    //   P  = sum e*es*t*sigma^2 (~ pdf * sum e)
    float S1 = 0.0f, S0 = 0.0f, P = 0.0f;
#pragma unroll
    for (int j = 0; j < 4; j++) {
        const float4 p4 = __ldcs(&pi4[base4 + j]);
        const float4 m4 = __ldcs(&mu4[base4 + j]);
        const float4 t4 = __ldcs(&s4[base4 + j]);

        const float pk[4] = {p4.x, p4.y, p4.z, p4.w};
        const float mk[4] = {m4.x, m4.y, m4.z, m4.w};
        const float sk[4] = {t4.x, t4.y, t4.z, t4.w};
#pragma unroll
        for (int q = 0; q < 4; q++) {
            const float ep = __expf(pk[q]);
            const float es = __expf(-sk[q]);
            const float z  = (x - mk[q]) * es;
            const float t  = __expf(-z);
            const float rc = __fdividef(1.0f, 1.0f + t);
            const float r1 = ep * rc;
            const float rt = r1 * t;
            S1 += r1;
            S0 += rt;
            P  += rt * (es * rc);
        }
    }

    // epilogue-only inputs (short live ranges)
    const float av  = __ldcs(&a[i]);
    const float bv  = __ldcs(&b[i]);
    const float xid = __ldcs(&x_id[i]);

    const float lS1 = __logf(S1);
    const float lS0 = __logf(S0);
    const float lSe = __logf(S1 + S0);
    const float lP  = __logf(P);

    // out = (log(S1/S0) + b) * exp(a);  ldj = lP + lSe - lS1 - lS0 + a
    __stcs(&out[i],    (lS1 - lS0 + bv) * __expf(av));
    __stcs(&out_id[i], xid);

    // ---- per-warp ldj reduction into device scratch accumulators ----
    float v = lP + lSe - lS1 - lS0 + av;
#pragma unroll
    for (int off = 16; off > 0; off >>= 1)
        v += __shfl_down_sync(0xFFFFFFFFu, v, off);
    if (lane == 0)
        atomicAdd(&g_acc[blockIdx.x >> 8], v);   // 256 blocks per batch

    // ---- completion-counter finalize (threadfence-reduction pattern) ----
    __syncthreads();                      // all warps' atomics issued
    __shared__ bool is_last;
    if (tid == 0) {
        __threadfence();                  // make this CTA's adds visible
        // atomicInc wraps to 0 after GRID increments -> self-resets each launch
        const unsigned old = atomicInc(&g_done, NBLK - 1);
        is_last = (old == NBLK - 1);
    }
    __syncthreads();
    if (is_last) {
        __threadfence();                  // acquire all CTAs' accumulations
        if (tid < BATCH) {
            const float acc = g_acc[tid];
            sldj_out[tid] = sldj_in[tid] + acc;
            g_acc[tid] = 0.0f;            // restore scratch for next launch
        }
    }
}

extern "C" void kernel_launch(void* const* d_in, const int* in_sizes, int n_in,
                              void* d_out, int out_size) {
    // Inputs (metadata order): x_change, x_id, sldj, a, b, pi, mu, s
    const float* x_change = (const float*)d_in[0];
    const float* x_id     = (const float*)d_in[1];
    const float* sldj     = (const float*)d_in[2];
    const float* a        = (const float*)d_in[3];
    const float* b        = (const float*)d_in[4];
    const float4* pi4     = (const float4*)d_in[5];
    const float4* mu4     = (const float4*)d_in[6];
    const float4* s4      = (const float4*)d_in[7];

    float* out      = (float*)d_out;
    float* out_id   = out + N_ELEM;
    float* sldj_out = out + 2 * N_ELEM;

    coupling_kernel<<<NBLK, TPB>>>(x_change, x_id, sldj, a, b,
                                   pi4, mu4, s4,
                                   out, out_id, sldj_out);
}

// round 13
// speedup vs baseline: 1.2159x; 1.2159x over previous
#include <cuda_runtime.h>
#include <math.h>

// Problem constants (B,C,H,W,K) = (32,8,64,64,16)
#define BATCH 32
#define CHW    (8 * 64 * 64)           // 32768 elements per batch
#define N_ELEM (BATCH * CHW)           // 1,048,576
#define KMIX   16
#define TPB    128
#define NBLK   (N_ELEM / TPB)          // 8192 logical tiles
#define NSM    148
#define GRID   (NSM * 12)              // persistent: one wave at 12 CTAs/SM

__global__ void init_sldj_kernel(const float* __restrict__ sldj_in,
                                 float* __restrict__ sldj_out) {
    int i = threadIdx.x;
    if (i < BATCH) sldj_out[i] = sldj_in[i];
}

__global__ void __launch_bounds__(TPB)
coupling_kernel(const float*  __restrict__ x_change,
                const float*  __restrict__ x_id,
                const float*  __restrict__ a,
                const float*  __restrict__ b,
                const float4* __restrict__ pi4,
                const float4* __restrict__ mu4,
                const float4* __restrict__ s4,
                float* __restrict__ out,       // [N_ELEM]
                float* __restrict__ out_id,    // [N_ELEM]
                float* __restrict__ sldj_out)  // [BATCH]
{
    const int tid  = threadIdx.x;
    const int lane = tid & 31;

    // Persistent grid-stride over logical tiles: one wave, no wave transitions,
    // and NO barriers anywhere in the loop (fire-and-forget stores + atomics).
    for (int blk = blockIdx.x; blk < NBLK; blk += GRID) {
        const int i = blk * TPB + tid;

        // ---- streaming loads (single-use, evict-first) ----
        const float x = __ldcs(&x_change[i]);

        const int base4 = i * (KMIX / 4);   // float4 index, fully coalesced

        // Linear-domain mixture accumulation:
        //   e_k = exp(pi_k), es_k = exp(-s_k), z_k = (x-mu_k)*es_k
        //   t_k = exp(-z_k), sigma_k = 1/(1+t_k)
        //   S1 = sum e*sigma        (~ cdf * sum e)
        //   S0 = sum e*t*sigma      (~ (1-cdf)*sum e;  S1+S0 == sum e exactly)
        //   P  = sum e*es*t*sigma^2 (~ pdf * sum e)
        float S1 = 0.0f, S0 = 0.0f, P = 0.0f;
#pragma unroll
        for (int j = 0; j < 4; j++) {
            const float4 p4 = __ldcs(&pi4[base4 + j]);
            const float4 m4 = __ldcs(&mu4[base4 + j]);
            const float4 t4 = __ldcs(&s4[base4 + j]);

            const float pk[4] = {p4.x, p4.y, p4.z, p4.w};
            const float mk[4] = {m4.x, m4.y, m4.z, m4.w};
            const float sk[4] = {t4.x, t4.y, t4.z, t4.w};
#pragma unroll
            for (int q = 0; q < 4; q++) {
                const float ep = __expf(pk[q]);
                const float es = __expf(-sk[q]);
                const float z  = (x - mk[q]) * es;
                const float t  = __expf(-z);
                const float rc = __fdividef(1.0f, 1.0f + t);
                const float r1 = ep * rc;
                const float rt = r1 * t;
                S1 += r1;
                S0 += rt;
                P  += rt * (es * rc);
            }
        }

        // epilogue-only inputs (short live ranges)
        const float av  = __ldcs(&a[i]);
        const float bv  = __ldcs(&b[i]);
        const float xid = __ldcs(&x_id[i]);

        const float lS1 = __logf(S1);
        const float lS0 = __logf(S0);
        const float lSe = __logf(S1 + S0);
        const float lP  = __logf(P);

        // out = (log(S1/S0) + b) * exp(a);  ldj = lP + lSe - lS1 - lS0 + a
        __stcs(&out[i],    (lS1 - lS0 + bv) * __expf(av));
        __stcs(&out_id[i], xid);

        // ---- per-warp ldj reduction, one fire-and-forget atomic per warp ----
        float v = lP + lSe - lS1 - lS0 + av;
#pragma unroll
        for (int off = 16; off > 0; off >>= 1)
            v += __shfl_down_sync(0xFFFFFFFFu, v, off);
        if (lane == 0)
            atomicAdd(&sldj_out[blk >> 8], v);   // 256 tiles per batch
    }
}

extern "C" void kernel_launch(void* const* d_in, const int* in_sizes, int n_in,
                              void* d_out, int out_size) {
    // Inputs (metadata order): x_change, x_id, sldj, a, b, pi, mu, s
    const float* x_change = (const float*)d_in[0];
    const float* x_id     = (const float*)d_in[1];
    const float* sldj     = (const float*)d_in[2];
    const float* a        = (const float*)d_in[3];
    const float* b        = (const float*)d_in[4];
    const float4* pi4     = (const float4*)d_in[5];
    const float4* mu4     = (const float4*)d_in[6];
    const float4* s4      = (const float4*)d_in[7];

    float* out      = (float*)d_out;
    float* out_id   = out + N_ELEM;
    float* sldj_out = out + 2 * N_ELEM;

    init_sldj_kernel<<<1, 32>>>(sldj, sldj_out);
    coupling_kernel<<<GRID, TPB>>>(x_change, x_id, a, b,
                                   pi4, mu4, s4,
                                   out, out_id, sldj_out);
}

// round 14
// speedup vs baseline: 1.5073x; 1.2397x over previous
#include <cuda_runtime.h>
#include <math.h>

// Problem constants (B,C,H,W,K) = (32,8,64,64,16)
#define BATCH 32
#define CHW    (8 * 64 * 64)           // 32768 elements per batch
#define N_ELEM (BATCH * CHW)           // 1,048,576
#define KMIX   16
#define TPB    128
#define NBLK   (N_ELEM / TPB)          // 8192 logical tiles
#define NSM    148
#define GRID   (NSM * 12)              // persistent: one wave at 12 CTAs/SM

__global__ void init_sldj_kernel(const float* __restrict__ sldj_in,
                                 float* __restrict__ sldj_out) {
    int i = threadIdx.x;
    if (i < BATCH) sldj_out[i] = sldj_in[i];
}

// R7 kernel verbatim — best measured kernel time (41.44 us).
__global__ void __launch_bounds__(TPB)
coupling_kernel(const float*  __restrict__ x_change,
                const float*  __restrict__ a,
                const float*  __restrict__ b,
                const float4* __restrict__ pi4,
                const float4* __restrict__ mu4,
                const float4* __restrict__ s4,
                float* __restrict__ out,       // [N_ELEM]
                float* __restrict__ sldj_out)  // [BATCH]
{
    __shared__ float warp_sums[TPB / 32];
    const int lane = threadIdx.x & 31;
    const int wid  = threadIdx.x >> 5;

    // Persistent grid-stride over logical blocks: one wave, no wave transitions.
    for (int blk = blockIdx.x; blk < NBLK; blk += GRID) {
        const int i = blk * TPB + threadIdx.x;

        // ---- streaming loads (single-use, evict-first) ----
        const float x = __ldcs(&x_change[i]);

        const int base4 = i * (KMIX / 4);   // float4 index, fully coalesced

        // Linear-domain mixture accumulation:
        //   e_k = exp(pi_k), es_k = exp(-s_k), z_k = (x-mu_k)*es_k
        //   t_k = exp(-z_k), sigma_k = 1/(1+t_k)
        //   S1 = sum e*sigma        (~ cdf * sum e)
        //   S0 = sum e*t*sigma      (~ (1-cdf)*sum e;  S1+S0 == sum e exactly)
        //   P  = sum e*es*t*sigma^2 (~ pdf * sum e)
        float S1 = 0.0f, S0 = 0.0f, P = 0.0f;
#pragma unroll
        for (int j = 0; j < 4; j++) {
            const float4 p4 = __ldcs(&pi4[base4 + j]);
            const float4 m4 = __ldcs(&mu4[base4 + j]);
            const float4 t4 = __ldcs(&s4[base4 + j]);

            const float pk[4] = {p4.x, p4.y, p4.z, p4.w};
            const float mk[4] = {m4.x, m4.y, m4.z, m4.w};
            const float sk[4] = {t4.x, t4.y, t4.z, t4.w};
#pragma unroll
            for (int q = 0; q < 4; q++) {
                const float ep = __expf(pk[q]);
                const float es = __expf(-sk[q]);
                const float z  = (x - mk[q]) * es;
                const float t  = __expf(-z);
                const float rc = __fdividef(1.0f, 1.0f + t);
                const float r1 = ep * rc;
                const float rt = r1 * t;
                S1 += r1;
                S0 += rt;
                P  += rt * (es * rc);
            }
        }

        // epilogue-only inputs loaded late (shorter live ranges in the loop)
        const float av = __ldcs(&a[i]);
        const float bv = __ldcs(&b[i]);

        const float lS1 = __logf(S1);
        const float lS0 = __logf(S0);
        const float lSe = __logf(S1 + S0);
        const float lP  = __logf(P);

        // out = (log(S1/S0) + b) * exp(a);  ldj = lP + lSe - lS1 - lS0 + a
        const float out_v    = (lS1 - lS0 + bv) * __expf(av);
        const float ldj_elem = lP + lSe - lS1 - lS0 + av;

        __stcs(&out[i], out_v);

        // ---- per-block reduction of ldj, one atomic per logical block ----
        float v = ldj_elem;
#pragma unroll
        for (int off = 16; off > 0; off >>= 1)
            v += __shfl_down_sync(0xFFFFFFFFu, v, off);

        if (lane == 0) warp_sums[wid] = v;
        __syncthreads();
        if (wid == 0) {
            float w = (lane < TPB / 32) ? warp_sums[lane] : 0.0f;
#pragma unroll
            for (int off = 2; off > 0; off >>= 1)
                w += __shfl_down_sync(0xFu, w, off);
            if (lane == 0) {
                const int batch = blk / (CHW / TPB);  // 256 logical blocks / batch
                atomicAdd(&sldj_out[batch], w);
            }
        }
        __syncthreads();   // warp_sums reuse across iterations
    }
}

extern "C" void kernel_launch(void* const* d_in, const int* in_sizes, int n_in,
                              void* d_out, int out_size) {
    // Inputs (metadata order): x_change, x_id, sldj, a, b, pi, mu, s
    const float* x_change = (const float*)d_in[0];
    const float* x_id     = (const float*)d_in[1];
    const float* sldj     = (const float*)d_in[2];
    const float* a        = (const float*)d_in[3];
    const float* b        = (const float*)d_in[4];
    const float4* pi4     = (const float4*)d_in[5];
    const float4* mu4     = (const float4*)d_in[6];
    const float4* s4      = (const float4*)d_in[7];

    float* out      = (float*)d_out;
    float* out_id   = out + N_ELEM;
    float* sldj_out = out + 2 * N_ELEM;

    // Side stream + events for a capture-forked parallel memcpy node.
    // Created once on the first (uncaptured correctness) call; host-side
    // objects only — no device memory allocation.
    static cudaStream_t s_copy = nullptr;
    static cudaEvent_t  e_fork = nullptr, e_join = nullptr;
    if (s_copy == nullptr) {
        cudaStreamCreateWithFlags(&s_copy, cudaStreamNonBlocking);
        cudaEventCreateWithFlags(&e_fork, cudaEventDisableTiming);
        cudaEventCreateWithFlags(&e_join, cudaEventDisableTiming);
    }

    // Fork: x_id passthrough runs as a parallel graph node (copy engine),
    // overlapping the main kernel instead of serializing after it.
    cudaEventRecord(e_fork, 0);
    cudaStreamWaitEvent(s_copy, e_fork, 0);
    cudaMemcpyAsync(out_id, x_id, N_ELEM * sizeof(float),
                    cudaMemcpyDeviceToDevice, s_copy);
    cudaEventRecord(e_join, s_copy);

    init_sldj_kernel<<<1, 32>>>(sldj, sldj_out);
    coupling_kernel<<<GRID, TPB>>>(x_change, a, b,
                                   pi4, mu4, s4,
                                   out, sldj_out);

    // Join: main stream waits for the copy before kernel_launch "completes".
    cudaStreamWaitEvent(0, e_join, 0);
}

// round 15
// speedup vs baseline: 1.6037x; 1.0639x over previous
#include <cuda_runtime.h>
#include <math.h>

// Problem constants (B,C,H,W,K) = (32,8,64,64,16)
#define BATCH 32
#define CHW    (8 * 64 * 64)           // 32768 elements per batch
#define N_ELEM (BATCH * CHW)           // 1,048,576
#define KMIX   16
#define TPB    128
#define NBLK   (N_ELEM / TPB)          // 8192 logical tiles
#define NSM    148
#define GRID   (NSM * 12)              // persistent: one wave at 12 CTAs/SM

__global__ void init_sldj_kernel(const float* __restrict__ sldj_in,
                                 float* __restrict__ sldj_out) {
    int i = threadIdx.x;
    if (i < BATCH) sldj_out[i] = sldj_in[i];
}

__global__ void __launch_bounds__(TPB)
coupling_kernel(const float*  __restrict__ x_change,
                const float*  __restrict__ x_id,
                const float*  __restrict__ a,
                const float*  __restrict__ b,
                const float4* __restrict__ pi4,
                const float4* __restrict__ mu4,
                const float4* __restrict__ s4,
                float* __restrict__ out,       // [N_ELEM]
                float* __restrict__ out_id,    // [N_ELEM]
                float* __restrict__ sldj_out)  // [BATCH]
{
    __shared__ float warp_sums[TPB / 32];
    const int lane = threadIdx.x & 31;
    const int wid  = threadIdx.x >> 5;

    // Persistent grid-stride over logical blocks: one wave, no wave transitions.
    for (int blk = blockIdx.x; blk < NBLK; blk += GRID) {
        const int i = blk * TPB + threadIdx.x;

        // ---- streaming loads (single-use, evict-first) ----
        const float x = __ldcs(&x_change[i]);

        const int base4 = i * (KMIX / 4);   // float4 index, fully coalesced

        // Linear-domain mixture accumulation:
        //   e_k = exp(pi_k), es_k = exp(-s_k), z_k = (x-mu_k)*es_k
        //   t_k = exp(-z_k), sigma_k = 1/(1+t_k)
        //   S1 = sum e*sigma        (~ cdf * sum e)
        //   S0 = sum e*t*sigma      (~ (1-cdf)*sum e;  S1+S0 == sum e exactly)
        //   P  = sum e*es*t*sigma^2 (~ pdf * sum e)
        float S1 = 0.0f, S0 = 0.0f, P = 0.0f;
#pragma unroll
        for (int j = 0; j < 4; j++) {
            const float4 p4 = __ldcs(&pi4[base4 + j]);
            const float4 m4 = __ldcs(&mu4[base4 + j]);
            const float4 t4 = __ldcs(&s4[base4 + j]);

            const float pk[4] = {p4.x, p4.y, p4.z, p4.w};
            const float mk[4] = {m4.x, m4.y, m4.z, m4.w};
            const float sk[4] = {t4.x, t4.y, t4.z, t4.w};
#pragma unroll
            for (int q = 0; q < 4; q++) {
                const float ep = __expf(pk[q]);
                const float es = __expf(-sk[q]);
                const float z  = (x - mk[q]) * es;
                const float t  = __expf(-z);
                const float rc = __fdividef(1.0f, 1.0f + t);
                const float r1 = ep * rc;
                const float rt = r1 * t;
                S1 += r1;
                S0 += rt;
                P  += rt * (es * rc);
            }
        }

        // epilogue-only inputs loaded late (shorter live ranges in the loop)
        const float av  = __ldcs(&a[i]);
        const float bv  = __ldcs(&b[i]);
        const float xid = __ldcs(&x_id[i]);

        const float lS1 = __logf(S1);
        const float lS0 = __logf(S0);
        const float lSe = __logf(S1 + S0);
        const float lP  = __logf(P);

        // out = (log(S1/S0) + b) * exp(a);  ldj = lP + lSe - lS1 - lS0 + a
        const float out_v    = (lS1 - lS0 + bv) * __expf(av);
        const float ldj_elem = lP + lSe - lS1 - lS0 + av;

        __stcs(&out[i],    out_v);
        __stcs(&out_id[i], xid);

        // ---- per-block reduction of ldj, one atomic per logical block ----
        float v = ldj_elem;
#pragma unroll
        for (int off = 16; off > 0; off >>= 1)
            v += __shfl_down_sync(0xFFFFFFFFu, v, off);

        if (lane == 0) warp_sums[wid] = v;
        __syncthreads();
        if (wid == 0) {
            float w = (lane < TPB / 32) ? warp_sums[lane] : 0.0f;
#pragma unroll
            for (int off = 2; off > 0; off >>= 1)
                w += __shfl_down_sync(0xFu, w, off);
            if (lane == 0) {
                const int batch = blk / (CHW / TPB);  // 256 logical blocks / batch
                atomicAdd(&sldj_out[batch], w);
            }
        }
        __syncthreads();   // warp_sums reuse across iterations
    }
}

extern "C" void kernel_launch(void* const* d_in, const int* in_sizes, int n_in,
                              void* d_out, int out_size) {
    // Inputs (metadata order): x_change, x_id, sldj, a, b, pi, mu, s
    const float* x_change = (const float*)d_in[0];
    const float* x_id     = (const float*)d_in[1];
    const float* sldj     = (const float*)d_in[2];
    const float* a        = (const float*)d_in[3];
    const float* b        = (const float*)d_in[4];
    const float4* pi4     = (const float4*)d_in[5];
    const float4* mu4     = (const float4*)d_in[6];
    const float4* s4      = (const float4*)d_in[7];

    float* out      = (float*)d_out;
    float* out_id   = out + N_ELEM;
    float* sldj_out = out + 2 * N_ELEM;

    init_sldj_kernel<<<1, 32>>>(sldj, sldj_out);
    coupling_kernel<<<GRID, TPB>>>(x_change, x_id, a, b,
                                   pi4, mu4, s4,
                                   out, out_id, sldj_out);
}

// round 16
// speedup vs baseline: 1.7613x; 1.0983x over previous
#include <cuda_runtime.h>
#include <math.h>

// Problem constants (B,C,H,W,K) = (32,8,64,64,16)
#define BATCH 32
#define CHW    (8 * 64 * 64)           // 32768 elements per batch
#define N_ELEM (BATCH * CHW)           // 1,048,576
#define KMIX   16
#define TPB    256
#define EPB    (TPB / 2)               // 128 elements per block (2 threads/elem)
#define NBLK   (N_ELEM / EPB)          // 8192 blocks

__global__ void init_sldj_kernel(const float* __restrict__ sldj_in,
                                 float* __restrict__ sldj_out) {
    int i = threadIdx.x;
    if (i < BATCH) sldj_out[i] = sldj_in[i];
}

// 8 CTAs/SM at TPB=256 -> 2048 threads/SM (100% theoretical occupancy).
// Split-K body only needs ~30 live regs, so the 32-reg cap is natural.
__global__ void __launch_bounds__(TPB, 8)
coupling_kernel(const float*  __restrict__ x_change,
                const float*  __restrict__ x_id,
                const float*  __restrict__ a,
                const float*  __restrict__ b,
                const float4* __restrict__ pi4,
                const float4* __restrict__ mu4,
                const float4* __restrict__ s4,
                float* __restrict__ out,       // [N_ELEM]
                float* __restrict__ out_id,    // [N_ELEM]
                float* __restrict__ sldj_out)  // [BATCH]
{
    const int tid  = threadIdx.x;
    const int half = tid & 1;                    // which 8 components
    const int e    = blockIdx.x * EPB + (tid >> 1);  // element index

    // Both partner threads read x (same address -> broadcast sectors).
    const float x = __ldcs(&x_change[e]);

    // This thread's 2 float4 chunks per tensor: consecutive across the pair,
    // so the warp still issues fully-coalesced 512B requests.
    const int base4 = e * (KMIX / 4) + half * 2;

    // Linear-domain mixture accumulation over THIS thread's 8 components:
    //   e_k = exp(pi_k), es_k = exp(-s_k), z_k = (x-mu_k)*es_k
    //   t_k = exp(-z_k), sigma_k = 1/(1+t_k)
    //   S1 = sum e*sigma, S0 = sum e*t*sigma, P = sum e*es*t*sigma^2
    float S1 = 0.0f, S0 = 0.0f, P = 0.0f;
#pragma unroll
    for (int j = 0; j < 2; j++) {
        const float4 p4 = __ldcs(&pi4[base4 + j]);
        const float4 m4 = __ldcs(&mu4[base4 + j]);
        const float4 t4 = __ldcs(&s4[base4 + j]);

        const float pk[4] = {p4.x, p4.y, p4.z, p4.w};
        const float mk[4] = {m4.x, m4.y, m4.z, m4.w};
        const float sk[4] = {t4.x, t4.y, t4.z, t4.w};
#pragma unroll
        for (int q = 0; q < 4; q++) {
            const float ep = __expf(pk[q]);
            const float es = __expf(-sk[q]);
            const float z  = (x - mk[q]) * es;
            const float t  = __expf(-z);
            const float rc = __fdividef(1.0f, 1.0f + t);
            const float r1 = ep * rc;
            const float rt = r1 * t;
            S1 += r1;
            S0 += rt;
            P  += rt * (es * rc);
        }
    }

    // Combine partner halves (lanes 2k <-> 2k+1). Sums are order-invariant,
    // so this matches the single-thread accumulation numerically.
    S1 += __shfl_xor_sync(0xFFFFFFFFu, S1, 1);
    S0 += __shfl_xor_sync(0xFFFFFFFFu, S0, 1);
    P  += __shfl_xor_sync(0xFFFFFFFFu, P,  1);

    // Epilogue on the even lane of each pair only.
    float ldj = 0.0f;
    if (half == 0) {
        const float av  = __ldcs(&a[e]);
        const float bv  = __ldcs(&b[e]);
        const float xid = __ldcs(&x_id[e]);

        const float lS1 = __logf(S1);
        const float lS0 = __logf(S0);
        const float lSe = __logf(S1 + S0);
        const float lP  = __logf(P);

        // out = (log(S1/S0) + b) * exp(a);  ldj = lP + lSe - lS1 - lS0 + a
        __stcs(&out[e],    (lS1 - lS0 + bv) * __expf(av));
        __stcs(&out_id[e], xid);
        ldj = lP + lSe - lS1 - lS0 + av;
    }

    // ---- per-block reduction of ldj, then one atomic per block ----
    float v = ldj;                         // odd lanes contribute 0
#pragma unroll
    for (int off = 16; off > 0; off >>= 1)
        v += __shfl_down_sync(0xFFFFFFFFu, v, off);

    __shared__ float warp_sums[TPB / 32];
    const int lane = tid & 31;
    const int wid  = tid >> 5;
    if (lane == 0) warp_sums[wid] = v;
    __syncthreads();
    if (wid == 0) {
        float w = (lane < TPB / 32) ? warp_sums[lane] : 0.0f;
#pragma unroll
        for (int off = 4; off > 0; off >>= 1)
            w += __shfl_down_sync(0xFFu, w, off);
        if (lane == 0) {
            const int batch = blockIdx.x / (CHW / EPB);  // 256 blocks per batch
            atomicAdd(&sldj_out[batch], w);
        }
    }
}

extern "C" void kernel_launch(void* const* d_in, const int* in_sizes, int n_in,
                              void* d_out, int out_size) {
    // Inputs (metadata order): x_change, x_id, sldj, a, b, pi, mu, s
    const float* x_change = (const float*)d_in[0];
    const float* x_id     = (const float*)d_in[1];
    const float* sldj     = (const float*)d_in[2];
    const float* a        = (const float*)d_in[3];
    const float* b        = (const float*)d_in[4];
    const float4* pi4     = (const float4*)d_in[5];
    const float4* mu4     = (const float4*)d_in[6];
    const float4* s4      = (const float4*)d_in[7];

    float* out      = (float*)d_out;
    float* out_id   = out + N_ELEM;
    float* sldj_out = out + 2 * N_ELEM;

    init_sldj_kernel<<<1, 32>>>(sldj, sldj_out);
    coupling_kernel<<<NBLK, TPB>>>(x_change, x_id, a, b,
                                   pi4, mu4, s4,
                                   out, out_id, sldj_out);
}